// round 10
// baseline (speedup 1.0000x reference)
#include <cuda_runtime.h>
#include <math.h>

typedef unsigned long long u64;

// ---------------- problem constants ----------------
#define N0v 16384
#define N1v 4096
#define N2v 1024
#define N3v 128
#define E0v 131072
#define E1v 32768
#define E2v 8192
#define E3v 1024
#define Bv  32

#define NO0 0
#define NO1 16384
#define NO2 20480
#define NO3 21504
#define NTOT 21632
#define RP0 0
#define RP1 16385
#define RP2 20482
#define RP3 21507
#define RPTOT 21640
#define EB0 0
#define EB1 131072
#define EB2 163840
#define EB3 172032
#define ETOT 173056

// ---------------- scratch ----------------
#define O_XT   0u
#define O_T1A  1572864u
#define O_H1   4718592u
#define O_T1B  8912896u
#define O_H2   17301504u
#define O_H3   18350080u
#define O_Y3   18481152u
#define O_FLAT 18612224u
#define O_F1   18743296u
#define O_F2   18874368u
#define O_F3   19005440u
#define O_END  19136512u

__device__ __align__(16) float g_buf[O_END];
__device__ int   g_deg[NTOT];
__device__ float g_dis[NTOT];
__device__ int   g_rowptr[RPTOT];
__device__ int   g_ctr[NTOT];
__device__ int2  g_ccw[ETOT];
__device__ float g_mu[Bv * 128];

// ---------------- f32x2 helpers ----------------
__device__ __forceinline__ u64 fma2(u64 a, u64 b, u64 c) {
    u64 d; asm("fma.rn.f32x2 %0,%1,%2,%3;" : "=l"(d) : "l"(a), "l"(b), "l"(c)); return d;
}
__device__ __forceinline__ u64 dup2(float x) {
    u64 d; unsigned u = __float_as_uint(x);
    asm("mov.b64 %0,{%1,%1};" : "=l"(d) : "r"(u)); return d;
}
__device__ __forceinline__ u64 pk2(float lo, float hi) {
    u64 d; asm("mov.b64 %0,{%1,%2};" : "=l"(d) : "r"(__float_as_uint(lo)), "r"(__float_as_uint(hi)));
    return d;
}
__device__ __forceinline__ float2 upk(u64 d) {
    unsigned lo, hi; asm("mov.b64 {%0,%1},%2;" : "=r"(lo), "=r"(hi) : "l"(d));
    return make_float2(__uint_as_float(lo), __uint_as_float(hi));
}

// ---------------- fused prep ----------------
#define PREP_EB 676
#define PREP_TB 128
#define PREP_ZB 384
#define PREP_MB 4
__global__ void k_prep(const int* __restrict__ e0, const int* __restrict__ e1,
                       const int* __restrict__ e2, const int* __restrict__ e3,
                       int* __restrict__ deg, const float* __restrict__ x,
                       float* __restrict__ xt, float* __restrict__ fz,
                       float* __restrict__ mu) {
    int b = blockIdx.x, t = threadIdx.x;
    if (b < PREP_EB) {
        int i = b * 256 + t;
        const int* e; int le, no;
        if (i < EB1)      { e = e0; le = i;       no = NO0; }
        else if (i < EB2) { e = e1; le = i - EB1; no = NO1; }
        else if (i < EB3) { e = e2; le = i - EB2; no = NO2; }
        else              { e = e3; le = i - EB3; no = NO3; }
        atomicAdd(&deg[no + e[le]], 1);
    } else if (b < PREP_EB + PREP_TB) {
        __shared__ float s[12288];
        int n0 = (b - PREP_EB) * 128;
        for (int i = t; i < 12288; i += 256) {
            int bb = i / 384, j = i - bb * 384;
            int nn = j / 3, c = j - nn * 3;
            s[nn * 96 + bb * 3 + c] = x[bb * 49152 + n0 * 3 + j];
        }
        __syncthreads();
        float4* dst = (float4*)(xt + (size_t)n0 * 96);
        const float4* src = (const float4*)s;
        for (int i = t; i < 3072; i += 256) dst[i] = src[i];
    } else if (b < PREP_EB + PREP_TB + PREP_ZB) {
        int i = (b - PREP_EB - PREP_TB) * 256 + t;
        ((float4*)fz)[i] = make_float4(0.f, 0.f, 0.f, 0.f);
    } else {
        int i = (b - PREP_EB - PREP_TB - PREP_ZB) * 256 + t;
        ((float4*)mu)[i] = make_float4(0.f, 0.f, 0.f, 0.f);
    }
}

// ---------------- scan (warp shuffle) + dis ----------------
__global__ void k_scan(const int* __restrict__ deg, float* __restrict__ dis,
                       int* __restrict__ rowptr, int* __restrict__ ctr) {
    __shared__ int wsum[32];
    int t = threadIdx.x, lane = t & 31, warp = t >> 5;
    const int no[4] = {NO0, NO1, NO2, NO3};
    const int Ns[4] = {N0v, N1v, N2v, N3v};
    const int rp[4] = {RP0, RP1, RP2, RP3};
    for (int lvl = 0; lvl < 4; lvl++) {
        int carry = 0;
        int Nn = Ns[lvl];
        for (int base = 0; base < Nn; base += 1024) {
            int idx = base + t;
            int v = (idx < Nn) ? deg[no[lvl] + idx] : 0;
            if (idx < Nn) dis[no[lvl] + idx] = (v > 0) ? rsqrtf((float)v) : 0.f;
            int p = v;
#pragma unroll
            for (int off = 1; off < 32; off <<= 1) {
                int u = __shfl_up_sync(0xffffffffu, p, off);
                if (lane >= off) p += u;
            }
            if (lane == 31) wsum[warp] = p;
            __syncthreads();
            if (warp == 0) {
                int s = wsum[lane];
#pragma unroll
                for (int off = 1; off < 32; off <<= 1) {
                    int u = __shfl_up_sync(0xffffffffu, s, off);
                    if (lane >= off) s += u;
                }
                wsum[lane] = s;
            }
            __syncthreads();
            int woff = (warp > 0) ? wsum[warp - 1] : 0;
            if (idx < Nn) {
                int excl = carry + woff + p - v;
                rowptr[rp[lvl] + idx] = excl;
                ctr[no[lvl] + idx] = excl;
            }
            carry += wsum[31];
            __syncthreads();
        }
        if (t == 0) rowptr[rp[lvl] + Nn] = carry;
    }
}

__global__ void k_scatter(const int* __restrict__ e0, const int* __restrict__ e1,
                          const int* __restrict__ e2, const int* __restrict__ e3,
                          const float* __restrict__ dis, int* __restrict__ ctr,
                          int2* __restrict__ ccw) {
    int t = blockIdx.x * 256 + threadIdx.x;
    if (t >= ETOT) return;
    const int* e; int le, no, E, eb;
    if (t < EB1)      { e = e0; le = t;       no = NO0; E = E0v; eb = EB0; }
    else if (t < EB2) { e = e1; le = t - EB1; no = NO1; E = E1v; eb = EB1; }
    else if (t < EB3) { e = e2; le = t - EB2; no = NO2; E = E2v; eb = EB2; }
    else              { e = e3; le = t - EB3; no = NO3; E = E3v; eb = EB3; }
    int row = e[le], col = e[E + le];
    float w = -dis[no + row] * dis[no + col];
    int pos = atomicAdd(&ctr[no + row], 1);
    ccw[eb + pos] = make_int2(col, __float_as_int(w));
}

// ---------------- prop96: warp per node, 4-edge unroll ----------------
__global__ void __launch_bounds__(256)
k_prop96(const float* __restrict__ in, float* __restrict__ out,
         const int* __restrict__ rp, const int2* __restrict__ ccw) {
    int wid = threadIdx.x >> 5, lane = threadIdx.x & 31;
    int n = blockIdx.x * 8 + wid;
    int s = rp[n], e = rp[n + 1];
    float a0 = 0.f, a1 = 0.f, a2 = 0.f;
    int i = s;
    for (; i + 4 <= e; i += 4) {
        int2 c0 = __ldg(&ccw[i]),     c1 = __ldg(&ccw[i + 1]);
        int2 c2 = __ldg(&ccw[i + 2]), c3 = __ldg(&ccw[i + 3]);
        const float* r0 = in + c0.x * 96;
        const float* r1 = in + c1.x * 96;
        const float* r2 = in + c2.x * 96;
        const float* r3 = in + c3.x * 96;
        float w0 = __int_as_float(c0.y), w1 = __int_as_float(c1.y);
        float w2 = __int_as_float(c2.y), w3 = __int_as_float(c3.y);
        a0 += w0 * r0[lane]      + w1 * r1[lane]      + w2 * r2[lane]      + w3 * r3[lane];
        a1 += w0 * r0[lane + 32] + w1 * r1[lane + 32] + w2 * r2[lane + 32] + w3 * r3[lane + 32];
        a2 += w0 * r0[lane + 64] + w1 * r1[lane + 64] + w2 * r2[lane + 64] + w3 * r3[lane + 64];
    }
    for (; i < e; i++) {
        int2 c0 = __ldg(&ccw[i]);
        const float* r0 = in + c0.x * 96;
        float w0 = __int_as_float(c0.y);
        a0 += w0 * r0[lane]; a1 += w0 * r0[lane + 32]; a2 += w0 * r0[lane + 64];
    }
    out[n * 96 + lane] = a0;
    out[n * 96 + lane + 32] = a1;
    out[n * 96 + lane + 64] = a2;
}

// ---------------- full prop (1024 floats/row), one node per block ---------
__global__ void __launch_bounds__(256)
k_prop1024(const float* __restrict__ in, float* __restrict__ out,
           const int* __restrict__ rp, const int2* __restrict__ ccw) {
    int n = blockIdx.x, t = threadIdx.x;
    int s = rp[n], e = rp[n + 1];
    const float4* in4 = (const float4*)in;
    float4 acc = make_float4(0.f, 0.f, 0.f, 0.f);
    int i = s;
    for (; i + 4 <= e; i += 4) {
        int2 a = __ldg(&ccw[i]),     bb = __ldg(&ccw[i + 1]);
        int2 c = __ldg(&ccw[i + 2]), d  = __ldg(&ccw[i + 3]);
        float4 u0 = in4[(size_t)a.x * 256 + t];
        float4 u1 = in4[(size_t)bb.x * 256 + t];
        float4 u2 = in4[(size_t)c.x * 256 + t];
        float4 u3 = in4[(size_t)d.x * 256 + t];
        float w0 = __int_as_float(a.y), w1 = __int_as_float(bb.y);
        float w2 = __int_as_float(c.y), w3 = __int_as_float(d.y);
        acc.x += w0 * u0.x + w1 * u1.x + w2 * u2.x + w3 * u3.x;
        acc.y += w0 * u0.y + w1 * u1.y + w2 * u2.y + w3 * u3.y;
        acc.z += w0 * u0.z + w1 * u1.z + w2 * u2.z + w3 * u3.z;
        acc.w += w0 * u0.w + w1 * u1.w + w2 * u2.w + w3 * u3.w;
    }
    for (; i < e; i++) {
        int2 cw = __ldg(&ccw[i]);
        float w = __int_as_float(cw.y);
        float4 v = in4[(size_t)cw.x * 256 + t];
        acc.x += w * v.x; acc.y += w * v.y; acc.z += w * v.z; acc.w += w * v.w;
    }
    ((float4*)out)[(size_t)n * 256 + t] = acc;
}

// ---------------- fused level-0 combine (gather P in-kernel) --------------
__global__ void __launch_bounds__(128)
k_comb0f(const float* __restrict__ X, const float* __restrict__ T1,
         const int* __restrict__ rp, const int2* __restrict__ ccw,
         const float* __restrict__ Wc, const float* __restrict__ bias,
         const int* __restrict__ pool, float* __restrict__ out) {
    __shared__ float s0[96], s1[96], s2[96], sW[288], sb[32];
    int p = blockIdx.x, t = threadIdx.x;
    int n = pool[p];
    for (int i = t; i < 288; i += 128) sW[i] = Wc[i];
    if (t < 32) sb[t] = bias[t];
    if (t < 96) {
        s0[t] = X[n * 96 + t];
        s1[t] = T1[n * 96 + t];
        int s = rp[n], e = rp[n + 1];
        float acc = 0.f;
        for (int i = s; i < e; i++) {
            int2 cw = __ldg(&ccw[i]);
            acc += __int_as_float(cw.y) * T1[cw.x * 96 + t];
        }
        s2[t] = acc;
    }
    __syncthreads();
#pragma unroll
    for (int j = 0; j < 8; j++) {
        int o = t + 128 * j;
        int b = o >> 5, f = o & 31;
        float acc = sb[f];
#pragma unroll
        for (int c = 0; c < 3; c++) {
            float x0 = s0[b * 3 + c];
            float x1 = s1[b * 3 + c];
            float x2 = 2.f * s2[b * 3 + c] - x0;
            acc += x0 * sW[c * 32 + f] + x1 * sW[96 + c * 32 + f] + x2 * sW[192 + c * 32 + f];
        }
        out[(size_t)p * 1024 + o] = acc;
    }
}

// ---------------- fused C=32 combine: gather P + cheb ----------------------
__global__ void __launch_bounds__(256)
k_comb32f(const float* __restrict__ Hh, const float* __restrict__ T1,
          const int* __restrict__ rp, const int2* __restrict__ ccw,
          const float* __restrict__ Wc, const float* __restrict__ bias,
          const int* __restrict__ pool, float* __restrict__ out,
          int doTanh, int flat) {
    __shared__ float w0s[1024], w1s[1024], w2s[1024], sb[32];
    __shared__ float sH[32 * 33], sT[32 * 33], sP[32 * 33];
    int t = threadIdx.x;
    for (int i = t; i < 1024; i += 256) {
        float a0 = Wc[i], a1 = Wc[1024 + i], a2 = Wc[2048 + i];
        w0s[i] = a0 - a2; w1s[i] = a1; w2s[i] = 2.f * a2;
    }
    if (t < 32) sb[t] = bias[t];
    int bq = t >> 3, c4 = (t & 7) * 4;
    const float4* T14 = (const float4*)T1;
    int p = blockIdx.x;
    int n = pool ? __ldg(&pool[p]) : p;
    int s = rp[n], e = rp[n + 1];
    float4 accP = make_float4(0.f, 0.f, 0.f, 0.f);
    int i = s;
    for (; i + 2 <= e; i += 2) {
        int2 a = __ldg(&ccw[i]), bb = __ldg(&ccw[i + 1]);
        float4 u0 = T14[(size_t)a.x * 256 + t];
        float4 u1 = T14[(size_t)bb.x * 256 + t];
        float w0 = __int_as_float(a.y), w1 = __int_as_float(bb.y);
        accP.x += w0 * u0.x + w1 * u1.x; accP.y += w0 * u0.y + w1 * u1.y;
        accP.z += w0 * u0.z + w1 * u1.z; accP.w += w0 * u0.w + w1 * u1.w;
    }
    for (; i < e; i++) {
        int2 a = __ldg(&ccw[i]);
        float4 u0 = T14[(size_t)a.x * 256 + t];
        float w0 = __int_as_float(a.y);
        accP.x += w0 * u0.x; accP.y += w0 * u0.y;
        accP.z += w0 * u0.z; accP.w += w0 * u0.w;
    }
    sP[bq * 33 + c4 + 0] = accP.x; sP[bq * 33 + c4 + 1] = accP.y;
    sP[bq * 33 + c4 + 2] = accP.z; sP[bq * 33 + c4 + 3] = accP.w;
    float4 vh = ((const float4*)Hh)[(size_t)n * 256 + t];
    sH[bq * 33 + c4 + 0] = vh.x; sH[bq * 33 + c4 + 1] = vh.y;
    sH[bq * 33 + c4 + 2] = vh.z; sH[bq * 33 + c4 + 3] = vh.w;
    float4 vt = T14[(size_t)n * 256 + t];
    sT[bq * 33 + c4 + 0] = vt.x; sT[bq * 33 + c4 + 1] = vt.y;
    sT[bq * 33 + c4 + 2] = vt.z; sT[bq * 33 + c4 + 3] = vt.w;
    __syncthreads();
    int b0 = (t >> 4) * 2, f0 = (t & 15) * 2;
    float a00 = sb[f0], a01 = sb[f0 + 1], a10 = sb[f0], a11 = sb[f0 + 1];
    for (int c = 0; c < 32; c++) {
        float h0 = sH[b0 * 33 + c],  h1 = sH[(b0 + 1) * 33 + c];
        float t0 = sT[b0 * 33 + c],  t1 = sT[(b0 + 1) * 33 + c];
        float p0 = sP[b0 * 33 + c],  p1 = sP[(b0 + 1) * 33 + c];
        float q0 = w0s[c * 32 + f0], q1 = w0s[c * 32 + f0 + 1];
        float r0 = w1s[c * 32 + f0], r1 = w1s[c * 32 + f0 + 1];
        float u0 = w2s[c * 32 + f0], u1 = w2s[c * 32 + f0 + 1];
        a00 += h0 * q0 + t0 * r0 + p0 * u0;
        a01 += h0 * q1 + t0 * r1 + p0 * u1;
        a10 += h1 * q0 + t1 * r0 + p1 * u0;
        a11 += h1 * q1 + t1 * r1 + p1 * u1;
    }
    if (doTanh) { a00 = tanhf(a00); a01 = tanhf(a01); a10 = tanhf(a10); a11 = tanhf(a11); }
    if (flat) {
        out[(size_t)b0 * 4096 + p * 32 + f0] = a00;
        out[(size_t)b0 * 4096 + p * 32 + f0 + 1] = a01;
        out[(size_t)(b0 + 1) * 4096 + p * 32 + f0] = a10;
        out[(size_t)(b0 + 1) * 4096 + p * 32 + f0 + 1] = a11;
    } else {
        out[(size_t)p * 1024 + b0 * 32 + f0] = a00;
        out[(size_t)p * 1024 + b0 * 32 + f0 + 1] = a01;
        out[(size_t)p * 1024 + (b0 + 1) * 32 + f0] = a10;
        out[(size_t)p * 1024 + (b0 + 1) * 32 + f0 + 1] = a11;
    }
}

// ---------------- FC: fused input-BN, X pre-staged, sync-free mainloop -----
// grid (8, FC_SPLITS), 256 thr. If g!=null: X := relu(bn(X; g,be)) per column.
#define FC_SPLITS 18
__global__ void __launch_bounds__(256)
k_fc3(const float* __restrict__ X, const float* __restrict__ W,
      float* __restrict__ out, const float* __restrict__ g,
      const float* __restrict__ be) {
    const int K = 4096, N = 4096;
    __shared__ u64 sX[232][17];
    int nbase = blockIdx.x * 512;
    int y = blockIdx.y;
    const int per = 512 / FC_SPLITS;        // 28
    const int rem = 512 % FC_SPLITS;        // 8
    int c0 = y * per + (y < rem ? y : rem);
    int myc = per + (y < rem ? 1 : 0);      // 28 or 29
    int kbase = c0 * 8;
    int ncols = myc * 8;                     // 224 or 232
    int t = threadIdx.x;
    int ct = t & 127, rgsel = t >> 7;
    int col = nbase + ct * 4;

    // Phase A: load this block's K-columns, apply BN+ReLU, pack into smem
    if (t < ncols) {
        float v[32];
#pragma unroll
        for (int m = 0; m < 32; m++) v[m] = X[(size_t)m * K + kbase + t];
        if (g) {
            float s = 0.f;
#pragma unroll
            for (int m = 0; m < 32; m++) s += v[m];
            float mean = s * (1.f / 32.f);
            float q = 0.f;
#pragma unroll
            for (int m = 0; m < 32; m++) { float d = v[m] - mean; q += d * d; }
            float inv = rsqrtf(q * (1.f / 32.f) + 1e-5f);
            float gg = g[kbase + t], bb = be[kbase + t];
#pragma unroll
            for (int m = 0; m < 32; m++)
                v[m] = fmaxf((v[m] - mean) * inv * gg + bb, 0.f);
        }
#pragma unroll
        for (int rp = 0; rp < 16; rp++)
            sX[t][rp] = pk2(v[2 * rp], v[2 * rp + 1]);
    }
    __syncthreads();

    u64 acc[8][4];
#pragma unroll
    for (int r = 0; r < 8; r++)
#pragma unroll
        for (int c = 0; c < 4; c++) acc[r][c] = 0ull;

    for (int c = 0; c < myc; c++) {
#pragma unroll
        for (int kk = 0; kk < 8; kk++) {
            int kl = c * 8 + kk;
            float4 w = *(const float4*)(W + (size_t)(kbase + kl) * N + col);
            u64 w0 = dup2(w.x), w1 = dup2(w.y), w2 = dup2(w.z), w3 = dup2(w.w);
#pragma unroll
            for (int r = 0; r < 8; r++) {
                u64 xv = sX[kl][rgsel * 8 + r];
                acc[r][0] = fma2(xv, w0, acc[r][0]);
                acc[r][1] = fma2(xv, w1, acc[r][1]);
                acc[r][2] = fma2(xv, w2, acc[r][2]);
                acc[r][3] = fma2(xv, w3, acc[r][3]);
            }
        }
    }
#pragma unroll
    for (int r = 0; r < 8; r++) {
        int re = rgsel * 16 + 2 * r;
#pragma unroll
        for (int c = 0; c < 4; c++) {
            float2 v = upk(acc[r][c]);
            atomicAdd(&out[(size_t)re * N + col + c], v.x);
            atomicAdd(&out[(size_t)(re + 1) * N + col + c], v.y);
        }
    }
}

// small final layer (N=128) with fused input-BN (g,be mandatory)
__global__ void __launch_bounds__(256)
k_fc2(const float* __restrict__ X, const float* __restrict__ W,
      float* __restrict__ out, const float* __restrict__ g,
      const float* __restrict__ be) {
    const int K = 4096, N = 128, KR = 128;
    __shared__ u64 sXbn[128][17];
    __shared__ u64 sWd[16][128];
    int k0 = blockIdx.y * KR;
    int t = threadIdx.x, cg = t & 31, rg = t >> 5;

    // Phase A: BN+ReLU this block's 128 K-columns
    if (t < 128) {
        float v[32];
#pragma unroll
        for (int m = 0; m < 32; m++) v[m] = X[(size_t)m * K + k0 + t];
        float s = 0.f;
#pragma unroll
        for (int m = 0; m < 32; m++) s += v[m];
        float mean = s * (1.f / 32.f);
        float q = 0.f;
#pragma unroll
        for (int m = 0; m < 32; m++) { float d = v[m] - mean; q += d * d; }
        float inv = rsqrtf(q * (1.f / 32.f) + 1e-5f);
        float gg = g[k0 + t], bb = be[k0 + t];
#pragma unroll
        for (int m = 0; m < 32; m++)
            v[m] = fmaxf((v[m] - mean) * inv * gg + bb, 0.f);
#pragma unroll
        for (int rp = 0; rp < 16; rp++)
            sXbn[t][rp] = pk2(v[2 * rp], v[2 * rp + 1]);
    }
    __syncthreads();

    u64 acc[2][4];
#pragma unroll
    for (int i = 0; i < 2; i++)
#pragma unroll
        for (int j = 0; j < 4; j++) acc[i][j] = 0ull;
    for (int kc = 0; kc < KR; kc += 16) {
#pragma unroll
        for (int h = 0; h < 2; h++) {
            int idx = t + 256 * h;
            int kk = idx >> 5, c4 = (idx & 31) * 4;
            float4 w = *(const float4*)(W + (size_t)(k0 + kc + kk) * N + c4);
            sWd[kk][c4 + 0] = dup2(w.x); sWd[kk][c4 + 1] = dup2(w.y);
            sWd[kk][c4 + 2] = dup2(w.z); sWd[kk][c4 + 3] = dup2(w.w);
        }
        __syncthreads();
#pragma unroll
        for (int kk = 0; kk < 16; kk++) {
            u64 x0 = sXbn[kc + kk][2 * rg];
            u64 x1 = sXbn[kc + kk][2 * rg + 1];
#pragma unroll
            for (int j = 0; j < 4; j++) {
                u64 w = sWd[kk][cg + 32 * j];
                acc[0][j] = fma2(x0, w, acc[0][j]);
                acc[1][j] = fma2(x1, w, acc[1][j]);
            }
        }
        __syncthreads();
    }
#pragma unroll
    for (int pr = 0; pr < 2; pr++)
#pragma unroll
        for (int j = 0; j < 4; j++) {
            float2 v = upk(acc[pr][j]);
            int col = cg + 32 * j;
            atomicAdd(&out[(size_t)(4 * rg + 2 * pr) * N + col], v.x);
            atomicAdd(&out[(size_t)(4 * rg + 2 * pr + 1) * N + col], v.y);
        }
}

// ---------------- final BatchNorm (no affine) + deg reset ----------------
__global__ void k_bnf(const float* __restrict__ in, float* __restrict__ out,
                      int* __restrict__ deg) {
    int f = blockIdx.x * blockDim.x + threadIdx.x;
    const int N = 128;
    if (f < N) {
        float v[32];
        float s = 0.f;
#pragma unroll
        for (int m = 0; m < 32; m++) { v[m] = in[(size_t)m * N + f]; s += v[m]; }
        float mean = s * (1.f / 32.f);
        float q = 0.f;
#pragma unroll
        for (int m = 0; m < 32; m++) { float d = v[m] - mean; q += d * d; }
        float inv = rsqrtf(q * (1.f / 32.f) + 1e-5f);
#pragma unroll
        for (int m = 0; m < 32; m++)
            out[(size_t)m * N + f] = (v[m] - mean) * inv;
    }
    // zero deg for the next call (graph replay); first call uses static init
    for (int i = f; i < NTOT; i += 128) deg[i] = 0;
}

// ---------------- host launcher ----------------
extern "C" void kernel_launch(void* const* d_in, const int* in_sizes, int n_in,
                              void* d_out, int out_size) {
    int map[32];
    bool dictOrder = (n_in > 1 && in_sizes[1] == 262144);
    if (dictOrder) {
        const int m[32] = {0, 8, 9, 10, 11, 12, 13, 14, 15, 16, 17, 18, 19, 20, 21,
                           22, 23, 24, 25, 26, 27, 28, 29, 30, 31, 1, 2, 3, 4, 5, 6, 7};
        for (int i = 0; i < 32; i++) map[i] = m[i];
    } else {
        for (int i = 0; i < 32; i++) map[i] = i;
    }
    const float* x   = (const float*)d_in[map[0]];
    const float* Wc1 = (const float*)d_in[map[1]];
    const float* b1  = (const float*)d_in[map[2]];
    const float* Wc2 = (const float*)d_in[map[3]];
    const float* b2  = (const float*)d_in[map[4]];
    const float* Wc3 = (const float*)d_in[map[5]];
    const float* b3  = (const float*)d_in[map[6]];
    const float* Wc4 = (const float*)d_in[map[7]];
    const float* b4  = (const float*)d_in[map[8]];
    const float* Wc5 = (const float*)d_in[map[9]];
    const float* b5  = (const float*)d_in[map[10]];
    const float* W6  = (const float*)d_in[map[11]];
    const float* g6  = (const float*)d_in[map[13]];
    const float* be6 = (const float*)d_in[map[14]];
    const float* W7  = (const float*)d_in[map[15]];
    const float* g7  = (const float*)d_in[map[17]];
    const float* be7 = (const float*)d_in[map[18]];
    const float* W8  = (const float*)d_in[map[19]];
    const float* g8  = (const float*)d_in[map[21]];
    const float* be8 = (const float*)d_in[map[22]];
    const float* W9  = (const float*)d_in[map[23]];
    const int* e0 = (const int*)d_in[map[25]];
    const int* e1 = (const int*)d_in[map[26]];
    const int* e2 = (const int*)d_in[map[27]];
    const int* e3 = (const int*)d_in[map[28]];
    const int* l0 = (const int*)d_in[map[29]];
    const int* l1 = (const int*)d_in[map[30]];
    const int* l2 = (const int*)d_in[map[31]];

    float *buf, *dis, *mu;
    int *deg, *rowptr, *ctr;
    int2* ccw;
    cudaGetSymbolAddress((void**)&buf, g_buf);
    cudaGetSymbolAddress((void**)&deg, g_deg);
    cudaGetSymbolAddress((void**)&dis, g_dis);
    cudaGetSymbolAddress((void**)&rowptr, g_rowptr);
    cudaGetSymbolAddress((void**)&ctr, g_ctr);
    cudaGetSymbolAddress((void**)&ccw, g_ccw);
    cudaGetSymbolAddress((void**)&mu, g_mu);

    float* XT   = buf + O_XT;
    float* T1A  = buf + O_T1A;
    float* H1   = buf + O_H1;
    float* T1B  = buf + O_T1B;
    float* H2   = buf + O_H2;
    float* H3   = buf + O_H3;
    float* Y3   = buf + O_Y3;
    float* FLAT = buf + O_FLAT;
    float* F1   = buf + O_F1;
    float* F2   = buf + O_F2;
    float* F3   = buf + O_F3;

    // ---- setup (deg is zeroed by the previous call's k_bnf / static init) --
    k_prep<<<PREP_EB + PREP_TB + PREP_ZB + PREP_MB, 256>>>(e0, e1, e2, e3, deg, x, XT, F1, mu);
    k_scan<<<1, 1024>>>(deg, dis, rowptr, ctr);
    k_scatter<<<(ETOT + 255) / 256, 256>>>(e0, e1, e2, e3, dis, ctr, ccw);

    // ---- level 0 (C=3): full prop, fused pooled-gather combine ----
    k_prop96<<<N0v / 8, 256>>>(XT, T1A, rowptr + RP0, ccw + EB0);
    k_comb0f<<<N1v, 128>>>(XT, T1A, rowptr + RP0, ccw + EB0, Wc1, b1, l0, H1);

    // ---- level 1 ----
    k_prop1024<<<N1v, 256>>>(H1, T1B, rowptr + RP1, ccw + EB1);
    k_comb32f<<<N2v, 256>>>(H1, T1B, rowptr + RP1, ccw + EB1, Wc2, b2, l1, H2, 1, 0);

    // ---- level 2 ----
    k_prop1024<<<N2v, 256>>>(H2, T1B, rowptr + RP2, ccw + EB2);
    k_comb32f<<<N3v, 256>>>(H2, T1B, rowptr + RP2, ccw + EB2, Wc3, b3, l2, H3, 1, 0);

    // ---- level 3a ----
    k_prop1024<<<N3v, 256>>>(H3, T1B, rowptr + RP3, ccw + EB3);
    k_comb32f<<<N3v, 256>>>(H3, T1B, rowptr + RP3, ccw + EB3, Wc4, b4, (const int*)0, Y3, 1, 0);

    // ---- level 3b ----
    k_prop1024<<<N3v, 256>>>(Y3, T1B, rowptr + RP3, ccw + EB3);
    k_comb32f<<<N3v, 256>>>(Y3, T1B, rowptr + RP3, ccw + EB3, Wc5, b5, (const int*)0, FLAT, 0, 1);

    // ---- FC stack (BN fused into consumer kernels) ----
    k_fc3<<<dim3(8, FC_SPLITS), 256>>>(FLAT, W6, F1, (const float*)0, (const float*)0);
    k_fc3<<<dim3(8, FC_SPLITS), 256>>>(F1, W7, F2, g6, be6);
    k_fc3<<<dim3(8, FC_SPLITS), 256>>>(F2, W8, F3, g7, be7);
    k_fc2<<<dim3(1, 32), 256>>>(F3, W9, mu, g8, be8);
    k_bnf<<<1, 128>>>(mu, (float*)d_out, deg);
}

// round 11
// speedup vs baseline: 1.4076x; 1.4076x over previous
#include <cuda_runtime.h>
#include <math.h>

typedef unsigned long long u64;

// ---------------- problem constants ----------------
#define N0v 16384
#define N1v 4096
#define N2v 1024
#define N3v 128
#define E0v 131072
#define E1v 32768
#define E2v 8192
#define E3v 1024
#define Bv  32

#define NO0 0
#define NO1 16384
#define NO2 20480
#define NO3 21504
#define NTOT 21632
#define RP0 0
#define RP1 16385
#define RP2 20482
#define RP3 21507
#define RPTOT 21640
#define EB0 0
#define EB1 131072
#define EB2 163840
#define EB3 172032
#define ETOT 173056

// ---------------- scratch ----------------
#define O_XT   0u
#define O_T1A  1572864u
#define O_H1   4718592u
#define O_T1B  8912896u
#define O_H2   17301504u
#define O_H3   18350080u
#define O_Y3   18481152u
#define O_FLAT 18612224u
#define O_F1   18743296u
#define O_F2   18874368u
#define O_F3   19005440u
#define O_END  19136512u

__device__ __align__(16) float g_buf[O_END];
__device__ int   g_deg[NTOT];
__device__ float g_dis[NTOT];
__device__ int   g_rowptr[RPTOT];
__device__ int   g_ctr[NTOT];
__device__ int2  g_ccw[ETOT];
__device__ float g_mu[Bv * 128];

// ---------------- f32x2 helpers ----------------
__device__ __forceinline__ u64 fma2(u64 a, u64 b, u64 c) {
    u64 d; asm("fma.rn.f32x2 %0,%1,%2,%3;" : "=l"(d) : "l"(a), "l"(b), "l"(c)); return d;
}
__device__ __forceinline__ u64 dup2(float x) {
    u64 d; unsigned u = __float_as_uint(x);
    asm("mov.b64 %0,{%1,%1};" : "=l"(d) : "r"(u)); return d;
}
__device__ __forceinline__ u64 pk2(float lo, float hi) {
    u64 d; asm("mov.b64 %0,{%1,%2};" : "=l"(d) : "r"(__float_as_uint(lo)), "r"(__float_as_uint(hi)));
    return d;
}
__device__ __forceinline__ float2 upk(u64 d) {
    unsigned lo, hi; asm("mov.b64 {%0,%1},%2;" : "=r"(lo), "=r"(hi) : "l"(d));
    return make_float2(__uint_as_float(lo), __uint_as_float(hi));
}

// ---------------- fused prep ----------------
#define PREP_EB 676
#define PREP_TB 128
#define PREP_ZB 384
#define PREP_MB 4
__global__ void k_prep(const int* __restrict__ e0, const int* __restrict__ e1,
                       const int* __restrict__ e2, const int* __restrict__ e3,
                       int* __restrict__ deg, const float* __restrict__ x,
                       float* __restrict__ xt, float* __restrict__ fz,
                       float* __restrict__ mu) {
    int b = blockIdx.x, t = threadIdx.x;
    if (b < PREP_EB) {
        int i = b * 256 + t;
        const int* e; int le, no;
        if (i < EB1)      { e = e0; le = i;       no = NO0; }
        else if (i < EB2) { e = e1; le = i - EB1; no = NO1; }
        else if (i < EB3) { e = e2; le = i - EB2; no = NO2; }
        else              { e = e3; le = i - EB3; no = NO3; }
        atomicAdd(&deg[no + e[le]], 1);
    } else if (b < PREP_EB + PREP_TB) {
        __shared__ float s[12288];
        int n0 = (b - PREP_EB) * 128;
        for (int i = t; i < 12288; i += 256) {
            int bb = i / 384, j = i - bb * 384;
            int nn = j / 3, c = j - nn * 3;
            s[nn * 96 + bb * 3 + c] = x[bb * 49152 + n0 * 3 + j];
        }
        __syncthreads();
        float4* dst = (float4*)(xt + (size_t)n0 * 96);
        const float4* src = (const float4*)s;
        for (int i = t; i < 3072; i += 256) dst[i] = src[i];
    } else if (b < PREP_EB + PREP_TB + PREP_ZB) {
        int i = (b - PREP_EB - PREP_TB) * 256 + t;
        ((float4*)fz)[i] = make_float4(0.f, 0.f, 0.f, 0.f);
    } else {
        int i = (b - PREP_EB - PREP_TB - PREP_ZB) * 256 + t;
        ((float4*)mu)[i] = make_float4(0.f, 0.f, 0.f, 0.f);
    }
}

// ---------------- scan (warp shuffle) + dis ----------------
__global__ void k_scan(const int* __restrict__ deg, float* __restrict__ dis,
                       int* __restrict__ rowptr, int* __restrict__ ctr) {
    __shared__ int wsum[32];
    int t = threadIdx.x, lane = t & 31, warp = t >> 5;
    const int no[4] = {NO0, NO1, NO2, NO3};
    const int Ns[4] = {N0v, N1v, N2v, N3v};
    const int rp[4] = {RP0, RP1, RP2, RP3};
    for (int lvl = 0; lvl < 4; lvl++) {
        int carry = 0;
        int Nn = Ns[lvl];
        for (int base = 0; base < Nn; base += 1024) {
            int idx = base + t;
            int v = (idx < Nn) ? deg[no[lvl] + idx] : 0;
            if (idx < Nn) dis[no[lvl] + idx] = (v > 0) ? rsqrtf((float)v) : 0.f;
            int p = v;
#pragma unroll
            for (int off = 1; off < 32; off <<= 1) {
                int u = __shfl_up_sync(0xffffffffu, p, off);
                if (lane >= off) p += u;
            }
            if (lane == 31) wsum[warp] = p;
            __syncthreads();
            if (warp == 0) {
                int s = wsum[lane];
#pragma unroll
                for (int off = 1; off < 32; off <<= 1) {
                    int u = __shfl_up_sync(0xffffffffu, s, off);
                    if (lane >= off) s += u;
                }
                wsum[lane] = s;
            }
            __syncthreads();
            int woff = (warp > 0) ? wsum[warp - 1] : 0;
            if (idx < Nn) {
                int excl = carry + woff + p - v;
                rowptr[rp[lvl] + idx] = excl;
                ctr[no[lvl] + idx] = excl;
            }
            carry += wsum[31];
            __syncthreads();
        }
        if (t == 0) rowptr[rp[lvl] + Nn] = carry;
    }
}

__global__ void k_scatter(const int* __restrict__ e0, const int* __restrict__ e1,
                          const int* __restrict__ e2, const int* __restrict__ e3,
                          const float* __restrict__ dis, int* __restrict__ ctr,
                          int2* __restrict__ ccw) {
    int t = blockIdx.x * 256 + threadIdx.x;
    if (t >= ETOT) return;
    const int* e; int le, no, E, eb;
    if (t < EB1)      { e = e0; le = t;       no = NO0; E = E0v; eb = EB0; }
    else if (t < EB2) { e = e1; le = t - EB1; no = NO1; E = E1v; eb = EB1; }
    else if (t < EB3) { e = e2; le = t - EB2; no = NO2; E = E2v; eb = EB2; }
    else              { e = e3; le = t - EB3; no = NO3; E = E3v; eb = EB3; }
    int row = e[le], col = e[E + le];
    float w = -dis[no + row] * dis[no + col];
    int pos = atomicAdd(&ctr[no + row], 1);
    ccw[eb + pos] = make_int2(col, __float_as_int(w));
}

// ---------------- prop96: warp per node, 4-edge unroll ----------------
__global__ void __launch_bounds__(256)
k_prop96(const float* __restrict__ in, float* __restrict__ out,
         const int* __restrict__ rp, const int2* __restrict__ ccw) {
    int wid = threadIdx.x >> 5, lane = threadIdx.x & 31;
    int n = blockIdx.x * 8 + wid;
    int s = rp[n], e = rp[n + 1];
    float a0 = 0.f, a1 = 0.f, a2 = 0.f;
    int i = s;
    for (; i + 4 <= e; i += 4) {
        int2 c0 = __ldg(&ccw[i]),     c1 = __ldg(&ccw[i + 1]);
        int2 c2 = __ldg(&ccw[i + 2]), c3 = __ldg(&ccw[i + 3]);
        const float* r0 = in + c0.x * 96;
        const float* r1 = in + c1.x * 96;
        const float* r2 = in + c2.x * 96;
        const float* r3 = in + c3.x * 96;
        float w0 = __int_as_float(c0.y), w1 = __int_as_float(c1.y);
        float w2 = __int_as_float(c2.y), w3 = __int_as_float(c3.y);
        a0 += w0 * r0[lane]      + w1 * r1[lane]      + w2 * r2[lane]      + w3 * r3[lane];
        a1 += w0 * r0[lane + 32] + w1 * r1[lane + 32] + w2 * r2[lane + 32] + w3 * r3[lane + 32];
        a2 += w0 * r0[lane + 64] + w1 * r1[lane + 64] + w2 * r2[lane + 64] + w3 * r3[lane + 64];
    }
    for (; i < e; i++) {
        int2 c0 = __ldg(&ccw[i]);
        const float* r0 = in + c0.x * 96;
        float w0 = __int_as_float(c0.y);
        a0 += w0 * r0[lane]; a1 += w0 * r0[lane + 32]; a2 += w0 * r0[lane + 64];
    }
    out[n * 96 + lane] = a0;
    out[n * 96 + lane + 32] = a1;
    out[n * 96 + lane + 64] = a2;
}

// ---------------- full prop (1024 floats/row), one node per block ---------
__global__ void __launch_bounds__(256)
k_prop1024(const float* __restrict__ in, float* __restrict__ out,
           const int* __restrict__ rp, const int2* __restrict__ ccw) {
    int n = blockIdx.x, t = threadIdx.x;
    int s = rp[n], e = rp[n + 1];
    const float4* in4 = (const float4*)in;
    float4 acc = make_float4(0.f, 0.f, 0.f, 0.f);
    int i = s;
    for (; i + 4 <= e; i += 4) {
        int2 a = __ldg(&ccw[i]),     bb = __ldg(&ccw[i + 1]);
        int2 c = __ldg(&ccw[i + 2]), d  = __ldg(&ccw[i + 3]);
        float4 u0 = in4[(size_t)a.x * 256 + t];
        float4 u1 = in4[(size_t)bb.x * 256 + t];
        float4 u2 = in4[(size_t)c.x * 256 + t];
        float4 u3 = in4[(size_t)d.x * 256 + t];
        float w0 = __int_as_float(a.y), w1 = __int_as_float(bb.y);
        float w2 = __int_as_float(c.y), w3 = __int_as_float(d.y);
        acc.x += w0 * u0.x + w1 * u1.x + w2 * u2.x + w3 * u3.x;
        acc.y += w0 * u0.y + w1 * u1.y + w2 * u2.y + w3 * u3.y;
        acc.z += w0 * u0.z + w1 * u1.z + w2 * u2.z + w3 * u3.z;
        acc.w += w0 * u0.w + w1 * u1.w + w2 * u2.w + w3 * u3.w;
    }
    for (; i < e; i++) {
        int2 cw = __ldg(&ccw[i]);
        float w = __int_as_float(cw.y);
        float4 v = in4[(size_t)cw.x * 256 + t];
        acc.x += w * v.x; acc.y += w * v.y; acc.z += w * v.z; acc.w += w * v.w;
    }
    ((float4*)out)[(size_t)n * 256 + t] = acc;
}

// ---------------- fused level-0 combine (gather P in-kernel) --------------
__global__ void __launch_bounds__(128)
k_comb0f(const float* __restrict__ X, const float* __restrict__ T1,
         const int* __restrict__ rp, const int2* __restrict__ ccw,
         const float* __restrict__ Wc, const float* __restrict__ bias,
         const int* __restrict__ pool, float* __restrict__ out) {
    __shared__ float s0[96], s1[96], s2[96], sW[288], sb[32];
    int p = blockIdx.x, t = threadIdx.x;
    int n = pool[p];
    for (int i = t; i < 288; i += 128) sW[i] = Wc[i];
    if (t < 32) sb[t] = bias[t];
    if (t < 96) {
        s0[t] = X[n * 96 + t];
        s1[t] = T1[n * 96 + t];
        int s = rp[n], e = rp[n + 1];
        float acc = 0.f;
        for (int i = s; i < e; i++) {
            int2 cw = __ldg(&ccw[i]);
            acc += __int_as_float(cw.y) * T1[cw.x * 96 + t];
        }
        s2[t] = acc;
    }
    __syncthreads();
#pragma unroll
    for (int j = 0; j < 8; j++) {
        int o = t + 128 * j;
        int b = o >> 5, f = o & 31;
        float acc = sb[f];
#pragma unroll
        for (int c = 0; c < 3; c++) {
            float x0 = s0[b * 3 + c];
            float x1 = s1[b * 3 + c];
            float x2 = 2.f * s2[b * 3 + c] - x0;
            acc += x0 * sW[c * 32 + f] + x1 * sW[96 + c * 32 + f] + x2 * sW[192 + c * 32 + f];
        }
        out[(size_t)p * 1024 + o] = acc;
    }
}

// ---------------- fused C=32 combine: gather P + cheb ----------------------
__global__ void __launch_bounds__(256)
k_comb32f(const float* __restrict__ Hh, const float* __restrict__ T1,
          const int* __restrict__ rp, const int2* __restrict__ ccw,
          const float* __restrict__ Wc, const float* __restrict__ bias,
          const int* __restrict__ pool, float* __restrict__ out,
          int doTanh, int flat) {
    __shared__ float w0s[1024], w1s[1024], w2s[1024], sb[32];
    __shared__ float sH[32 * 33], sT[32 * 33], sP[32 * 33];
    int t = threadIdx.x;
    for (int i = t; i < 1024; i += 256) {
        float a0 = Wc[i], a1 = Wc[1024 + i], a2 = Wc[2048 + i];
        w0s[i] = a0 - a2; w1s[i] = a1; w2s[i] = 2.f * a2;
    }
    if (t < 32) sb[t] = bias[t];
    int bq = t >> 3, c4 = (t & 7) * 4;
    const float4* T14 = (const float4*)T1;
    int p = blockIdx.x;
    int n = pool ? __ldg(&pool[p]) : p;
    int s = rp[n], e = rp[n + 1];
    float4 accP = make_float4(0.f, 0.f, 0.f, 0.f);
    int i = s;
    for (; i + 2 <= e; i += 2) {
        int2 a = __ldg(&ccw[i]), bb = __ldg(&ccw[i + 1]);
        float4 u0 = T14[(size_t)a.x * 256 + t];
        float4 u1 = T14[(size_t)bb.x * 256 + t];
        float w0 = __int_as_float(a.y), w1 = __int_as_float(bb.y);
        accP.x += w0 * u0.x + w1 * u1.x; accP.y += w0 * u0.y + w1 * u1.y;
        accP.z += w0 * u0.z + w1 * u1.z; accP.w += w0 * u0.w + w1 * u1.w;
    }
    for (; i < e; i++) {
        int2 a = __ldg(&ccw[i]);
        float4 u0 = T14[(size_t)a.x * 256 + t];
        float w0 = __int_as_float(a.y);
        accP.x += w0 * u0.x; accP.y += w0 * u0.y;
        accP.z += w0 * u0.z; accP.w += w0 * u0.w;
    }
    sP[bq * 33 + c4 + 0] = accP.x; sP[bq * 33 + c4 + 1] = accP.y;
    sP[bq * 33 + c4 + 2] = accP.z; sP[bq * 33 + c4 + 3] = accP.w;
    float4 vh = ((const float4*)Hh)[(size_t)n * 256 + t];
    sH[bq * 33 + c4 + 0] = vh.x; sH[bq * 33 + c4 + 1] = vh.y;
    sH[bq * 33 + c4 + 2] = vh.z; sH[bq * 33 + c4 + 3] = vh.w;
    float4 vt = T14[(size_t)n * 256 + t];
    sT[bq * 33 + c4 + 0] = vt.x; sT[bq * 33 + c4 + 1] = vt.y;
    sT[bq * 33 + c4 + 2] = vt.z; sT[bq * 33 + c4 + 3] = vt.w;
    __syncthreads();
    int b0 = (t >> 4) * 2, f0 = (t & 15) * 2;
    float a00 = sb[f0], a01 = sb[f0 + 1], a10 = sb[f0], a11 = sb[f0 + 1];
    for (int c = 0; c < 32; c++) {
        float h0 = sH[b0 * 33 + c],  h1 = sH[(b0 + 1) * 33 + c];
        float t0 = sT[b0 * 33 + c],  t1 = sT[(b0 + 1) * 33 + c];
        float p0 = sP[b0 * 33 + c],  p1 = sP[(b0 + 1) * 33 + c];
        float q0 = w0s[c * 32 + f0], q1 = w0s[c * 32 + f0 + 1];
        float r0 = w1s[c * 32 + f0], r1 = w1s[c * 32 + f0 + 1];
        float u0 = w2s[c * 32 + f0], u1 = w2s[c * 32 + f0 + 1];
        a00 += h0 * q0 + t0 * r0 + p0 * u0;
        a01 += h0 * q1 + t0 * r1 + p0 * u1;
        a10 += h1 * q0 + t1 * r0 + p1 * u0;
        a11 += h1 * q1 + t1 * r1 + p1 * u1;
    }
    if (doTanh) { a00 = tanhf(a00); a01 = tanhf(a01); a10 = tanhf(a10); a11 = tanhf(a11); }
    if (flat) {
        out[(size_t)b0 * 4096 + p * 32 + f0] = a00;
        out[(size_t)b0 * 4096 + p * 32 + f0 + 1] = a01;
        out[(size_t)(b0 + 1) * 4096 + p * 32 + f0] = a10;
        out[(size_t)(b0 + 1) * 4096 + p * 32 + f0 + 1] = a11;
    } else {
        out[(size_t)p * 1024 + b0 * 32 + f0] = a00;
        out[(size_t)p * 1024 + b0 * 32 + f0 + 1] = a01;
        out[(size_t)p * 1024 + (b0 + 1) * 32 + f0] = a10;
        out[(size_t)p * 1024 + (b0 + 1) * 32 + f0 + 1] = a11;
    }
}

// ---------------- FC: fused input-BN + pipelined W prefetch ----------------
// grid (8, FC_SPLITS), 256 thr. If g!=null: X := relu(bn(X; g,be)) per column.
#define FC_SPLITS 18
__global__ void __launch_bounds__(256)
k_fc3(const float* __restrict__ X, const float* __restrict__ W,
      float* __restrict__ out, const float* __restrict__ g,
      const float* __restrict__ be) {
    const int K = 4096, N = 4096;
    __shared__ u64 sX[232][17];
    int nbase = blockIdx.x * 512;
    int y = blockIdx.y;
    const int per = 512 / FC_SPLITS;        // 28
    const int rem = 512 % FC_SPLITS;        // 8
    int c0 = y * per + (y < rem ? y : rem);
    int myc = per + (y < rem ? 1 : 0);      // 28 or 29
    int kbase = c0 * 8;
    int ncols = myc * 8;                     // 224 or 232
    int t = threadIdx.x;
    int ct = t & 127, rgsel = t >> 7;
    int col = nbase + ct * 4;

    // Phase A: load this block's K-columns, apply BN+ReLU, pack into smem
    if (t < ncols) {
        float v[32];
#pragma unroll
        for (int m = 0; m < 32; m++) v[m] = X[(size_t)m * K + kbase + t];
        if (g) {
            float s = 0.f;
#pragma unroll
            for (int m = 0; m < 32; m++) s += v[m];
            float mean = s * (1.f / 32.f);
            float q = 0.f;
#pragma unroll
            for (int m = 0; m < 32; m++) { float d = v[m] - mean; q += d * d; }
            float inv = rsqrtf(q * (1.f / 32.f) + 1e-5f);
            float gg = g[kbase + t], bb = be[kbase + t];
#pragma unroll
            for (int m = 0; m < 32; m++)
                v[m] = fmaxf((v[m] - mean) * inv * gg + bb, 0.f);
        }
#pragma unroll
        for (int rp = 0; rp < 16; rp++)
            sX[t][rp] = pk2(v[2 * rp], v[2 * rp + 1]);
    }
    __syncthreads();

    u64 acc[8][4];
#pragma unroll
    for (int r = 0; r < 8; r++)
#pragma unroll
        for (int c = 0; c < 4; c++) acc[r][c] = 0ull;

    // Pipelined mainloop: prefetch next chunk's W into regs during compute
    float4 wc[8];
#pragma unroll
    for (int kk = 0; kk < 8; kk++)
        wc[kk] = *(const float4*)(W + (size_t)(kbase + kk) * N + col);

    for (int c = 0; c < myc; c++) {
        float4 wn[8];
        bool more = (c + 1 < myc);
        if (more) {
#pragma unroll
            for (int kk = 0; kk < 8; kk++)
                wn[kk] = *(const float4*)(W + (size_t)(kbase + (c + 1) * 8 + kk) * N + col);
        }
#pragma unroll
        for (int kk = 0; kk < 8; kk++) {
            int kl = c * 8 + kk;
            u64 w0 = dup2(wc[kk].x), w1 = dup2(wc[kk].y);
            u64 w2 = dup2(wc[kk].z), w3 = dup2(wc[kk].w);
#pragma unroll
            for (int r = 0; r < 8; r++) {
                u64 xv = sX[kl][rgsel * 8 + r];
                acc[r][0] = fma2(xv, w0, acc[r][0]);
                acc[r][1] = fma2(xv, w1, acc[r][1]);
                acc[r][2] = fma2(xv, w2, acc[r][2]);
                acc[r][3] = fma2(xv, w3, acc[r][3]);
            }
        }
        if (more) {
#pragma unroll
            for (int kk = 0; kk < 8; kk++) wc[kk] = wn[kk];
        }
    }
#pragma unroll
    for (int r = 0; r < 8; r++) {
        int re = rgsel * 16 + 2 * r;
#pragma unroll
        for (int c = 0; c < 4; c++) {
            float2 v = upk(acc[r][c]);
            atomicAdd(&out[(size_t)re * N + col + c], v.x);
            atomicAdd(&out[(size_t)(re + 1) * N + col + c], v.y);
        }
    }
}

// small final layer (N=128) with fused input-BN (g,be mandatory)
__global__ void __launch_bounds__(256)
k_fc2(const float* __restrict__ X, const float* __restrict__ W,
      float* __restrict__ out, const float* __restrict__ g,
      const float* __restrict__ be) {
    const int K = 4096, N = 128, KR = 128;
    __shared__ u64 sXbn[128][17];
    __shared__ u64 sWd[16][128];
    int k0 = blockIdx.y * KR;
    int t = threadIdx.x, cg = t & 31, rg = t >> 5;

    // Phase A: BN+ReLU this block's 128 K-columns
    if (t < 128) {
        float v[32];
#pragma unroll
        for (int m = 0; m < 32; m++) v[m] = X[(size_t)m * K + k0 + t];
        float s = 0.f;
#pragma unroll
        for (int m = 0; m < 32; m++) s += v[m];
        float mean = s * (1.f / 32.f);
        float q = 0.f;
#pragma unroll
        for (int m = 0; m < 32; m++) { float d = v[m] - mean; q += d * d; }
        float inv = rsqrtf(q * (1.f / 32.f) + 1e-5f);
        float gg = g[k0 + t], bb = be[k0 + t];
#pragma unroll
        for (int m = 0; m < 32; m++)
            v[m] = fmaxf((v[m] - mean) * inv * gg + bb, 0.f);
#pragma unroll
        for (int rp = 0; rp < 16; rp++)
            sXbn[t][rp] = pk2(v[2 * rp], v[2 * rp + 1]);
    }
    __syncthreads();

    u64 acc[2][4];
#pragma unroll
    for (int i = 0; i < 2; i++)
#pragma unroll
        for (int j = 0; j < 4; j++) acc[i][j] = 0ull;
    for (int kc = 0; kc < KR; kc += 16) {
#pragma unroll
        for (int h = 0; h < 2; h++) {
            int idx = t + 256 * h;
            int kk = idx >> 5, c4 = (idx & 31) * 4;
            float4 w = *(const float4*)(W + (size_t)(k0 + kc + kk) * N + c4);
            sWd[kk][c4 + 0] = dup2(w.x); sWd[kk][c4 + 1] = dup2(w.y);
            sWd[kk][c4 + 2] = dup2(w.z); sWd[kk][c4 + 3] = dup2(w.w);
        }
        __syncthreads();
#pragma unroll
        for (int kk = 0; kk < 16; kk++) {
            u64 x0 = sXbn[kc + kk][2 * rg];
            u64 x1 = sXbn[kc + kk][2 * rg + 1];
#pragma unroll
            for (int j = 0; j < 4; j++) {
                u64 w = sWd[kk][cg + 32 * j];
                acc[0][j] = fma2(x0, w, acc[0][j]);
                acc[1][j] = fma2(x1, w, acc[1][j]);
            }
        }
        __syncthreads();
    }
#pragma unroll
    for (int pr = 0; pr < 2; pr++)
#pragma unroll
        for (int j = 0; j < 4; j++) {
            float2 v = upk(acc[pr][j]);
            int col = cg + 32 * j;
            atomicAdd(&out[(size_t)(4 * rg + 2 * pr) * N + col], v.x);
            atomicAdd(&out[(size_t)(4 * rg + 2 * pr + 1) * N + col], v.y);
        }
}

// ---------------- final BatchNorm (no affine) + deg reset ----------------
__global__ void k_bnf(const float* __restrict__ in, float* __restrict__ out,
                      int* __restrict__ deg) {
    int f = blockIdx.x * blockDim.x + threadIdx.x;
    const int N = 128;
    if (f < N) {
        float v[32];
        float s = 0.f;
#pragma unroll
        for (int m = 0; m < 32; m++) { v[m] = in[(size_t)m * N + f]; s += v[m]; }
        float mean = s * (1.f / 32.f);
        float q = 0.f;
#pragma unroll
        for (int m = 0; m < 32; m++) { float d = v[m] - mean; q += d * d; }
        float inv = rsqrtf(q * (1.f / 32.f) + 1e-5f);
#pragma unroll
        for (int m = 0; m < 32; m++)
            out[(size_t)m * N + f] = (v[m] - mean) * inv;
    }
    for (int i = f; i < NTOT; i += 128) deg[i] = 0;
}

// ---------------- host launcher ----------------
extern "C" void kernel_launch(void* const* d_in, const int* in_sizes, int n_in,
                              void* d_out, int out_size) {
    int map[32];
    bool dictOrder = (n_in > 1 && in_sizes[1] == 262144);
    if (dictOrder) {
        const int m[32] = {0, 8, 9, 10, 11, 12, 13, 14, 15, 16, 17, 18, 19, 20, 21,
                           22, 23, 24, 25, 26, 27, 28, 29, 30, 31, 1, 2, 3, 4, 5, 6, 7};
        for (int i = 0; i < 32; i++) map[i] = m[i];
    } else {
        for (int i = 0; i < 32; i++) map[i] = i;
    }
    const float* x   = (const float*)d_in[map[0]];
    const float* Wc1 = (const float*)d_in[map[1]];
    const float* b1  = (const float*)d_in[map[2]];
    const float* Wc2 = (const float*)d_in[map[3]];
    const float* b2  = (const float*)d_in[map[4]];
    const float* Wc3 = (const float*)d_in[map[5]];
    const float* b3  = (const float*)d_in[map[6]];
    const float* Wc4 = (const float*)d_in[map[7]];
    const float* b4  = (const float*)d_in[map[8]];
    const float* Wc5 = (const float*)d_in[map[9]];
    const float* b5  = (const float*)d_in[map[10]];
    const float* W6  = (const float*)d_in[map[11]];
    const float* g6  = (const float*)d_in[map[13]];
    const float* be6 = (const float*)d_in[map[14]];
    const float* W7  = (const float*)d_in[map[15]];
    const float* g7  = (const float*)d_in[map[17]];
    const float* be7 = (const float*)d_in[map[18]];
    const float* W8  = (const float*)d_in[map[19]];
    const float* g8  = (const float*)d_in[map[21]];
    const float* be8 = (const float*)d_in[map[22]];
    const float* W9  = (const float*)d_in[map[23]];
    const int* e0 = (const int*)d_in[map[25]];
    const int* e1 = (const int*)d_in[map[26]];
    const int* e2 = (const int*)d_in[map[27]];
    const int* e3 = (const int*)d_in[map[28]];
    const int* l0 = (const int*)d_in[map[29]];
    const int* l1 = (const int*)d_in[map[30]];
    const int* l2 = (const int*)d_in[map[31]];

    float *buf, *dis, *mu;
    int *deg, *rowptr, *ctr;
    int2* ccw;
    cudaGetSymbolAddress((void**)&buf, g_buf);
    cudaGetSymbolAddress((void**)&deg, g_deg);
    cudaGetSymbolAddress((void**)&dis, g_dis);
    cudaGetSymbolAddress((void**)&rowptr, g_rowptr);
    cudaGetSymbolAddress((void**)&ctr, g_ctr);
    cudaGetSymbolAddress((void**)&ccw, g_ccw);
    cudaGetSymbolAddress((void**)&mu, g_mu);

    float* XT   = buf + O_XT;
    float* T1A  = buf + O_T1A;
    float* H1   = buf + O_H1;
    float* T1B  = buf + O_T1B;
    float* H2   = buf + O_H2;
    float* H3   = buf + O_H3;
    float* Y3   = buf + O_Y3;
    float* FLAT = buf + O_FLAT;
    float* F1   = buf + O_F1;
    float* F2   = buf + O_F2;
    float* F3   = buf + O_F3;

    // ---- setup (deg is zeroed by the previous call's k_bnf / static init) --
    k_prep<<<PREP_EB + PREP_TB + PREP_ZB + PREP_MB, 256>>>(e0, e1, e2, e3, deg, x, XT, F1, mu);
    k_scan<<<1, 1024>>>(deg, dis, rowptr, ctr);
    k_scatter<<<(ETOT + 255) / 256, 256>>>(e0, e1, e2, e3, dis, ctr, ccw);

    // ---- level 0 (C=3): full prop, fused pooled-gather combine ----
    k_prop96<<<N0v / 8, 256>>>(XT, T1A, rowptr + RP0, ccw + EB0);
    k_comb0f<<<N1v, 128>>>(XT, T1A, rowptr + RP0, ccw + EB0, Wc1, b1, l0, H1);

    // ---- level 1 ----
    k_prop1024<<<N1v, 256>>>(H1, T1B, rowptr + RP1, ccw + EB1);
    k_comb32f<<<N2v, 256>>>(H1, T1B, rowptr + RP1, ccw + EB1, Wc2, b2, l1, H2, 1, 0);

    // ---- level 2 ----
    k_prop1024<<<N2v, 256>>>(H2, T1B, rowptr + RP2, ccw + EB2);
    k_comb32f<<<N3v, 256>>>(H2, T1B, rowptr + RP2, ccw + EB2, Wc3, b3, l2, H3, 1, 0);

    // ---- level 3a ----
    k_prop1024<<<N3v, 256>>>(H3, T1B, rowptr + RP3, ccw + EB3);
    k_comb32f<<<N3v, 256>>>(H3, T1B, rowptr + RP3, ccw + EB3, Wc4, b4, (const int*)0, Y3, 1, 0);

    // ---- level 3b ----
    k_prop1024<<<N3v, 256>>>(Y3, T1B, rowptr + RP3, ccw + EB3);
    k_comb32f<<<N3v, 256>>>(Y3, T1B, rowptr + RP3, ccw + EB3, Wc5, b5, (const int*)0, FLAT, 0, 1);

    // ---- FC stack (BN fused into consumers, pipelined W prefetch) ----
    k_fc3<<<dim3(8, FC_SPLITS), 256>>>(FLAT, W6, F1, (const float*)0, (const float*)0);
    k_fc3<<<dim3(8, FC_SPLITS), 256>>>(F1, W7, F2, g6, be6);
    k_fc3<<<dim3(8, FC_SPLITS), 256>>>(F2, W8, F3, g7, be7);
    k_fc2<<<dim3(1, 32), 256>>>(F3, W9, mu, g8, be8);
    k_bnf<<<1, 128>>>(mu, (float*)d_out, deg);
}